// round 1
// baseline (speedup 1.0000x reference)
#include <cuda_runtime.h>
#include <math.h>
#include <stdint.h>

// Problem constants
#define CB   2
#define CL   2048
#define CE   2048
#define CH   32
#define CHKV 8
#define CD   64
#define CM   (CB*CL)          // 4096 rows for all GEMMs
#define KVE  (CHKV*CD)        // 512

// Scratch (allocation-free rule: __device__ globals)
__device__ float g_q  [CB*CL*CE];
__device__ float g_k  [CB*CL*KVE];
__device__ float g_v  [CB*CL*KVE];
__device__ float g_ctx[CB*CL*CE];

// ---------------------------------------------------------------------------
// SGEMM: C[M,N] = A[M,K] @ W[K,N] (+ bias). BM=BN=128, BK=8, 256 threads,
// 8x8 per-thread microtile. All dims divisible by tile sizes for this problem.
// ---------------------------------------------------------------------------
template<bool BIAS>
__global__ __launch_bounds__(256)
void sgemm128(const float* __restrict__ A, const float* __restrict__ W,
              const float* __restrict__ bias, float* __restrict__ C,
              int M, int N, int K)
{
    __shared__ float As[8][128];
    __shared__ float Bs[8][128];

    const int tid = threadIdx.x;
    const int tx  = tid & 15;
    const int ty  = tid >> 4;
    const int row0 = blockIdx.y * 128;
    const int col0 = blockIdx.x * 128;

    const int arow = tid >> 1;          // 0..127
    const int acol = (tid & 1) * 4;     // 0 or 4
    const int brow = tid >> 5;          // 0..7
    const int bcol = (tid & 31) * 4;    // 0..124

    const float* Aptr = A + (size_t)(row0 + arow) * K + acol;
    const float* Wptr = W + (size_t)brow * N + col0 + bcol;

    float acc[8][8];
#pragma unroll
    for (int i = 0; i < 8; i++)
#pragma unroll
        for (int j = 0; j < 8; j++) acc[i][j] = 0.f;

    for (int k0 = 0; k0 < K; k0 += 8) {
        float4 a  = *(const float4*)Aptr;  Aptr += 8;
        float4 bb = *(const float4*)Wptr;  Wptr += (size_t)8 * N;

        As[acol + 0][arow] = a.x;
        As[acol + 1][arow] = a.y;
        As[acol + 2][arow] = a.z;
        As[acol + 3][arow] = a.w;
        *(float4*)&Bs[brow][bcol] = bb;
        __syncthreads();

#pragma unroll
        for (int kk = 0; kk < 8; kk++) {
            float4 a0 = *(const float4*)&As[kk][ty * 8];
            float4 a1 = *(const float4*)&As[kk][ty * 8 + 4];
            float4 b0 = *(const float4*)&Bs[kk][tx * 8];
            float4 b1 = *(const float4*)&Bs[kk][tx * 8 + 4];
            float ar[8] = {a0.x, a0.y, a0.z, a0.w, a1.x, a1.y, a1.z, a1.w};
            float br[8] = {b0.x, b0.y, b0.z, b0.w, b1.x, b1.y, b1.z, b1.w};
#pragma unroll
            for (int i = 0; i < 8; i++)
#pragma unroll
                for (int j = 0; j < 8; j++) acc[i][j] += ar[i] * br[j];
        }
        __syncthreads();
    }

#pragma unroll
    for (int i = 0; i < 8; i++) {
        int row = row0 + ty * 8 + i;
        float* dst = C + (size_t)row * N + col0 + tx * 8;
#pragma unroll
        for (int j4 = 0; j4 < 8; j4 += 4) {
            float4 o;
            o.x = acc[i][j4 + 0]; o.y = acc[i][j4 + 1];
            o.z = acc[i][j4 + 2]; o.w = acc[i][j4 + 3];
            if (BIAS) {
                const float* bp = bias + col0 + tx * 8 + j4;
                o.x += bp[0]; o.y += bp[1]; o.z += bp[2]; o.w += bp[3];
            }
            *(float4*)(dst + j4) = o;
        }
    }
}

// ---------------------------------------------------------------------------
// RoPE in place. x layout (B, L, Hn, D), interleaved even/odd rotation.
// One thread per (even,odd) pair -> pair index p maps to elements 2p, 2p+1.
// ---------------------------------------------------------------------------
__global__ void rope_kernel(float* __restrict__ x, int Hn, int npairs)
{
    int p = blockIdx.x * blockDim.x + threadIdx.x;
    if (p >= npairs) return;
    int d2   = p & 31;                 // D/2 = 32
    int rest = p >> 5;
    int l    = (rest / Hn) % CL;       // sequence position

    // inv_freq = 10000^(-(2*d2)/64)
    float inv = expf(-(float)(2 * d2) * (9.210340371976184f / 64.f));
    float fr  = (float)l * inv;
    float s, c;
    sincosf(fr, &s, &c);               // accurate range reduction (fr up to ~2047)

    size_t base = (size_t)p * 2;
    float xe = x[base], xo = x[base + 1];
    x[base]     = xe * c - xo * s;
    x[base + 1] = xe * s + xo * c;
}

// ---------------------------------------------------------------------------
// Causal GQA flash attention. Tile 64(q) x 64(kv), D=64. 256 threads,
// 4x4 per-thread microtiles, online softmax staged through smem.
// grid = (L/64, B*H)
// ---------------------------------------------------------------------------
#define ATT_ST 65
#define ATT_SMEM_BYTES (4 * 64 * ATT_ST * 4 + 3 * 64 * 4)   // 67328 B

__global__ __launch_bounds__(256)
void attn_kernel(const float* __restrict__ q, const float* __restrict__ k,
                 const float* __restrict__ v, float* __restrict__ ctx)
{
    const int qt  = blockIdx.x;        // q tile 0..31
    const int bh  = blockIdx.y;        // 0..63
    const int b   = bh >> 5;
    const int h   = bh & 31;
    const int hkv = h >> 2;            // KV_GROUP = 4

    const int tid = threadIdx.x;
    const int tx  = tid & 15;
    const int ty  = tid >> 4;
    const int r0  = ty * 4;
    const int c0  = tx * 4;

    extern __shared__ float sm[];
    float* Qs  = sm;
    float* Ks  = sm + 1 * 64 * ATT_ST;
    float* Vs  = sm + 2 * 64 * ATT_ST;
    float* Ss  = sm + 3 * 64 * ATT_ST;
    float* m_s = sm + 4 * 64 * ATT_ST;
    float* l_s = m_s + 64;
    float* c_s = l_s + 64;

    // Load Q tile (64 rows x 64 d)
    {
        int r  = tid >> 2;
        int d0 = (tid & 3) * 16;
        const float* src = q + (((size_t)(b * CL + qt * 64 + r)) * CH + h) * CD + d0;
#pragma unroll
        for (int i = 0; i < 16; i += 4) {
            float4 t = *(const float4*)(src + i);
            Qs[r * ATT_ST + d0 + i + 0] = t.x;
            Qs[r * ATT_ST + d0 + i + 1] = t.y;
            Qs[r * ATT_ST + d0 + i + 2] = t.z;
            Qs[r * ATT_ST + d0 + i + 3] = t.w;
        }
    }
    if (tid < 64) { m_s[tid] = -1e30f; l_s[tid] = 0.f; }

    float acc[4][4];
#pragma unroll
    for (int i = 0; i < 4; i++)
#pragma unroll
        for (int j = 0; j < 4; j++) acc[i][j] = 0.f;

    for (int jt = 0; jt <= qt; ++jt) {
        __syncthreads();   // protect Ks/Vs/Ss from previous iteration readers

        // Load K and V tiles (64 x 64 each)
        {
            int r  = tid >> 2;
            int d0 = (tid & 3) * 16;
            size_t goff = (((size_t)(b * CL + jt * 64 + r)) * CHKV + hkv) * CD + d0;
            const float* ksrc = k + goff;
            const float* vsrc = v + goff;
#pragma unroll
            for (int i = 0; i < 16; i += 4) {
                float4 t = *(const float4*)(ksrc + i);
                Ks[r * ATT_ST + d0 + i + 0] = t.x;
                Ks[r * ATT_ST + d0 + i + 1] = t.y;
                Ks[r * ATT_ST + d0 + i + 2] = t.z;
                Ks[r * ATT_ST + d0 + i + 3] = t.w;
                float4 u = *(const float4*)(vsrc + i);
                Vs[r * ATT_ST + d0 + i + 0] = u.x;
                Vs[r * ATT_ST + d0 + i + 1] = u.y;
                Vs[r * ATT_ST + d0 + i + 2] = u.z;
                Vs[r * ATT_ST + d0 + i + 3] = u.w;
            }
        }
        __syncthreads();

        // S = Q K^T for this tile
        float s[4][4];
#pragma unroll
        for (int i = 0; i < 4; i++)
#pragma unroll
            for (int j = 0; j < 4; j++) s[i][j] = 0.f;

#pragma unroll 4
        for (int d = 0; d < 64; d++) {
            float av[4], bv[4];
#pragma unroll
            for (int i = 0; i < 4; i++) av[i] = Qs[(r0 + i) * ATT_ST + d];
#pragma unroll
            for (int j = 0; j < 4; j++) bv[j] = Ks[(c0 + j) * ATT_ST + d];
#pragma unroll
            for (int i = 0; i < 4; i++)
#pragma unroll
                for (int j = 0; j < 4; j++) s[i][j] += av[i] * bv[j];
        }

        const bool diag = (jt == qt);
#pragma unroll
        for (int i = 0; i < 4; i++)
#pragma unroll
            for (int j = 0; j < 4; j++) {
                float val = s[i][j] * 0.125f;            // 1/sqrt(64)
                if (diag && (c0 + j > r0 + i)) val = -1e30f;
                Ss[(r0 + i) * ATT_ST + c0 + j] = val;
            }
        __syncthreads();

        // Online softmax, one thread per row
        if (tid < 64) {
            float* row = Ss + tid * ATT_ST;
            float mold = m_s[tid];
            float mm = mold;
#pragma unroll 8
            for (int c = 0; c < 64; c++) mm = fmaxf(mm, row[c]);
            float corr = __expf(mold - mm);
            float sum = 0.f;
#pragma unroll 8
            for (int c = 0; c < 64; c++) {
                float pv = __expf(row[c] - mm);
                row[c] = pv;
                sum += pv;
            }
            l_s[tid] = l_s[tid] * corr + sum;
            m_s[tid] = mm;
            c_s[tid] = corr;
        }
        __syncthreads();

        // Rescale accumulators and O += P @ V
        float cf[4];
#pragma unroll
        for (int i = 0; i < 4; i++) cf[i] = c_s[r0 + i];
#pragma unroll
        for (int i = 0; i < 4; i++)
#pragma unroll
            for (int j = 0; j < 4; j++) acc[i][j] *= cf[i];

#pragma unroll 4
        for (int kk = 0; kk < 64; kk++) {
            float vv[4];
#pragma unroll
            for (int j = 0; j < 4; j++) vv[j] = Vs[kk * ATT_ST + c0 + j];
#pragma unroll
            for (int i = 0; i < 4; i++) {
                float pv = Ss[(r0 + i) * ATT_ST + kk];
#pragma unroll
                for (int j = 0; j < 4; j++) acc[i][j] += pv * vv[j];
            }
        }
    }

    // Finalize and store ctx in (B, L, H, D) layout (== (B, L, E) reshape)
    float invl[4];
#pragma unroll
    for (int i = 0; i < 4; i++) invl[i] = 1.f / l_s[r0 + i];

#pragma unroll
    for (int i = 0; i < 4; i++) {
        size_t base = (((size_t)(b * CL + qt * 64 + r0 + i)) * CH + h) * CD + c0;
#pragma unroll
        for (int j = 0; j < 4; j++)
            ctx[base + j] = acc[i][j] * invl[i];
    }
}

// ---------------------------------------------------------------------------
// Launch
// ---------------------------------------------------------------------------
extern "C" void kernel_launch(void* const* d_in, const int* in_sizes, int n_in,
                              void* d_out, int out_size)
{
    const float* q_in = (const float*)d_in[0];
    const float* k_in = (const float*)d_in[1];
    const float* v_in = (const float*)d_in[2];
    // d_in[3] = attn_mask (causal tril, hardcoded in attn kernel)
    const float* Wq = (const float*)d_in[4];
    const float* Wk = (const float*)d_in[5];
    const float* Wv = (const float*)d_in[6];
    const float* Wo = (const float*)d_in[7];
    const float* bo = (const float*)d_in[8];
    float* out = (float*)d_out;

    float *pq, *pk, *pv, *pctx;
    cudaGetSymbolAddress((void**)&pq,   g_q);
    cudaGetSymbolAddress((void**)&pk,   g_k);
    cudaGetSymbolAddress((void**)&pv,   g_v);
    cudaGetSymbolAddress((void**)&pctx, g_ctx);

    cudaFuncSetAttribute(attn_kernel, cudaFuncAttributeMaxDynamicSharedMemorySize,
                         ATT_SMEM_BYTES);

    // Projections
    dim3 gq(CE / 128, CM / 128);      // 16 x 32
    sgemm128<false><<<gq, 256>>>(q_in, Wq, nullptr, pq, CM, CE, CE);
    dim3 gkv(KVE / 128, CM / 128);    // 4 x 32
    sgemm128<false><<<gkv, 256>>>(k_in, Wk, nullptr, pk, CM, KVE, CE);
    sgemm128<false><<<gkv, 256>>>(v_in, Wv, nullptr, pv, CM, KVE, CE);

    // RoPE on q and k
    {
        int npq = CB * CL * CH * (CD / 2);     // 4,194,304
        rope_kernel<<<(npq + 255) / 256, 256>>>(pq, CH, npq);
        int npk = CB * CL * CHKV * (CD / 2);   // 1,048,576
        rope_kernel<<<(npk + 255) / 256, 256>>>(pk, CHKV, npk);
    }

    // Attention
    dim3 ga(CL / 64, CB * CH);        // 32 x 64
    attn_kernel<<<ga, 256, ATT_SMEM_BYTES>>>(pq, pk, pv, pctx);

    // Output projection + bias
    sgemm128<true><<<gq, 256>>>(pctx, Wo, bo, out, CM, CE, CE);
}

// round 3
// speedup vs baseline: 2.0025x; 2.0025x over previous
#include <cuda_runtime.h>
#include <math.h>
#include <stdint.h>

// Problem constants
#define CB   2
#define CL   2048
#define CE   2048
#define CH   32
#define CHKV 8
#define CD   64
#define CM   (CB*CL)          // 4096 rows for all GEMMs
#define KVE  (CHKV*CD)        // 512

// Scratch (allocation-free rule: __device__ globals)
__device__ float g_q  [CB*CL*CE];
__device__ float g_k  [CB*CL*KVE];
__device__ float g_v  [CB*CL*KVE];
__device__ float g_ctx[CB*CL*CE];

// ---------------------------------------------------------------------------
// Helpers
// ---------------------------------------------------------------------------
__device__ __forceinline__ uint32_t f2t(float x) {
    uint32_t r;
    asm("cvt.rna.tf32.f32 %0, %1;" : "=r"(r) : "f"(x));
    return r;
}
__device__ __forceinline__ float f2tf(float x) { return __uint_as_float(f2t(x)); }

__device__ __forceinline__ void mma8(float* c, const uint32_t* a, const uint32_t* b) {
    asm volatile(
        "mma.sync.aligned.m16n8k8.row.col.f32.tf32.tf32.f32 "
        "{%0,%1,%2,%3},{%4,%5,%6,%7},{%8,%9},{%0,%1,%2,%3};"
        : "+f"(c[0]), "+f"(c[1]), "+f"(c[2]), "+f"(c[3])
        : "r"(a[0]), "r"(a[1]), "r"(a[2]), "r"(a[3]), "r"(b[0]), "r"(b[1]));
}

// ---------------------------------------------------------------------------
// tf32 tensor-core GEMM: C[M,N] = A[M,K] @ W[K,N] (+bias).
// BM=BN=128, BK=16, 256 threads (8 warps, 2x4), 4x4 m16n8k8 tiles per warp.
// ---------------------------------------------------------------------------
template<bool BIAS>
__global__ __launch_bounds__(256)
void tgemm(const float* __restrict__ A, const float* __restrict__ W,
           const float* __restrict__ bias, float* __restrict__ C,
           int M, int N, int K)
{
    __shared__ float As[16][132];   // As[k][m]  (transposed A tile)
    __shared__ float Bs[16][132];   // Bs[k][n]

    const int tid  = threadIdx.x;
    const int lane = tid & 31;
    const int warp = tid >> 5;
    const int g = lane >> 2;        // groupID
    const int q = lane & 3;         // threadID_in_group
    const int wm = (warp & 1) * 64;
    const int wn = (warp >> 1) * 32;
    const int row0 = blockIdx.y * 128;
    const int col0 = blockIdx.x * 128;

    const int lr = tid >> 1;            // A load row 0..127
    const int lc = (tid & 1) * 8;       // A load k offset 0/8
    const int bkr = tid >> 4;           // B load k row 0..15
    const int bn  = (tid & 15) * 8;     // B load n offset

    float acc[4][4][4];
#pragma unroll
    for (int mt = 0; mt < 4; mt++)
#pragma unroll
        for (int nt = 0; nt < 4; nt++)
#pragma unroll
            for (int i = 0; i < 4; i++) acc[mt][nt][i] = 0.f;

    const float* Ap = A + (size_t)(row0 + lr) * K + lc;
    const float* Wp = W + (size_t)bkr * N + col0 + bn;

    for (int k0 = 0; k0 < K; k0 += 16) {
        float4 a0 = *(const float4*)(Ap);
        float4 a1 = *(const float4*)(Ap + 4);
        Ap += 16;
        float4 b0 = *(const float4*)(Wp);
        float4 b1 = *(const float4*)(Wp + 4);
        Wp += (size_t)16 * N;

        As[lc + 0][lr] = f2tf(a0.x);
        As[lc + 1][lr] = f2tf(a0.y);
        As[lc + 2][lr] = f2tf(a0.z);
        As[lc + 3][lr] = f2tf(a0.w);
        As[lc + 4][lr] = f2tf(a1.x);
        As[lc + 5][lr] = f2tf(a1.y);
        As[lc + 6][lr] = f2tf(a1.z);
        As[lc + 7][lr] = f2tf(a1.w);

        float4 cb0, cb1;
        cb0.x = f2tf(b0.x); cb0.y = f2tf(b0.y); cb0.z = f2tf(b0.z); cb0.w = f2tf(b0.w);
        cb1.x = f2tf(b1.x); cb1.y = f2tf(b1.y); cb1.z = f2tf(b1.z); cb1.w = f2tf(b1.w);
        *(float4*)&Bs[bkr][bn]     = cb0;
        *(float4*)&Bs[bkr][bn + 4] = cb1;
        __syncthreads();

#pragma unroll
        for (int ks = 0; ks < 2; ks++) {
            const int kk = ks * 8;
            uint32_t af[4][4], bf[4][2];
#pragma unroll
            for (int mt = 0; mt < 4; mt++) {
                int m = wm + mt * 16 + g;
                af[mt][0] = __float_as_uint(As[kk + q][m]);
                af[mt][1] = __float_as_uint(As[kk + q][m + 8]);
                af[mt][2] = __float_as_uint(As[kk + q + 4][m]);
                af[mt][3] = __float_as_uint(As[kk + q + 4][m + 8]);
            }
#pragma unroll
            for (int nt = 0; nt < 4; nt++) {
                int n = wn + nt * 8 + g;
                bf[nt][0] = __float_as_uint(Bs[kk + q][n]);
                bf[nt][1] = __float_as_uint(Bs[kk + q + 4][n]);
            }
#pragma unroll
            for (int mt = 0; mt < 4; mt++)
#pragma unroll
                for (int nt = 0; nt < 4; nt++)
                    mma8(acc[mt][nt], af[mt], bf[nt]);
        }
        __syncthreads();
    }

#pragma unroll
    for (int mt = 0; mt < 4; mt++) {
#pragma unroll
        for (int nt = 0; nt < 4; nt++) {
            int r = row0 + wm + mt * 16 + g;
            int c = col0 + wn + nt * 8 + 2 * q;
            float2 v0 = {acc[mt][nt][0], acc[mt][nt][1]};
            float2 v1 = {acc[mt][nt][2], acc[mt][nt][3]};
            if (BIAS) {
                v0.x += bias[c]; v0.y += bias[c + 1];
                v1.x += bias[c]; v1.y += bias[c + 1];
            }
            *(float2*)(C + (size_t)r * N + c)       = v0;
            *(float2*)(C + (size_t)(r + 8) * N + c) = v1;
        }
    }
}

// ---------------------------------------------------------------------------
// RoPE in place. x layout (B, L, Hn, D), pairwise even/odd rotation.
// ---------------------------------------------------------------------------
__global__ void rope_kernel(float* __restrict__ x, int Hn, int npairs)
{
    int p = blockIdx.x * blockDim.x + threadIdx.x;
    if (p >= npairs) return;
    int d2   = p & 31;                 // D/2 = 32
    int rest = p >> 5;
    int l    = (rest / Hn) % CL;

    float inv = expf(-(float)(2 * d2) * (9.210340371976184f / 64.f));
    float fr  = (float)l * inv;
    float s, c;
    sincosf(fr, &s, &c);

    size_t base = (size_t)p * 2;
    float xe = x[base], xo = x[base + 1];
    x[base]     = xe * c - xo * s;
    x[base + 1] = xe * s + xo * c;
}

// ---------------------------------------------------------------------------
// Causal GQA flash attention with tf32 tensor cores.
// Tile 64(q) x 64(kv), D=64, 256 threads (8 warps: 4 row-groups x 2 col-groups).
// grid = (L/64, B*H)
// ---------------------------------------------------------------------------
#define AP 68
#define ATT_SMEM_BYTES (4 * 64 * AP * 4 + 3 * 64 * 4)   // 70400 B

__global__ __launch_bounds__(256)
void attn_kernel(const float* __restrict__ q, const float* __restrict__ k,
                 const float* __restrict__ v, float* __restrict__ ctx)
{
    const int qt  = blockIdx.x;
    const int bh  = blockIdx.y;
    const int b   = bh >> 5;
    const int h   = bh & 31;
    const int hkv = h >> 2;

    const int tid  = threadIdx.x;
    const int lane = tid & 31;
    const int warp = tid >> 5;
    const int g = lane >> 2;
    const int qq = lane & 3;
    const int sm0 = (warp & 3) * 16;     // S/O row base (16 rows per warp grp)
    const int sn0 = (warp >> 2) * 32;    // S col base / O col base

    extern __shared__ float sm[];
    float* Qs  = sm;                 // [64][AP]
    float* Ks  = Qs + 64 * AP;
    float* Vs  = Ks + 64 * AP;
    float* Ss  = Vs + 64 * AP;
    float* m_s = Ss + 64 * AP;
    float* l_s = m_s + 64;
    float* c_s = l_s + 64;

    // Load Q tile (tf32-rounded)
    {
        int r  = tid >> 2;
        int d0 = (tid & 3) * 16;
        const float* src = q + (((size_t)(b * CL + qt * 64 + r)) * CH + h) * CD + d0;
#pragma unroll
        for (int i = 0; i < 16; i += 4) {
            float4 t = *(const float4*)(src + i);
            float4 ct = {f2tf(t.x), f2tf(t.y), f2tf(t.z), f2tf(t.w)};
            *(float4*)&Qs[r * AP + d0 + i] = ct;
        }
    }
    if (tid < 64) { m_s[tid] = -1e30f; l_s[tid] = 0.f; }

    float oa[4][4];
#pragma unroll
    for (int nt = 0; nt < 4; nt++)
#pragma unroll
        for (int i = 0; i < 4; i++) oa[nt][i] = 0.f;

    for (int jt = 0; jt <= qt; ++jt) {
        __syncthreads();   // protect Ks/Vs/Ss from previous iteration readers

        // Load K and V tiles (tf32-rounded)
        {
            int r  = tid >> 2;
            int d0 = (tid & 3) * 16;
            size_t goff = (((size_t)(b * CL + jt * 64 + r)) * CHKV + hkv) * CD + d0;
            const float* ksrc = k + goff;
            const float* vsrc = v + goff;
#pragma unroll
            for (int i = 0; i < 16; i += 4) {
                float4 t = *(const float4*)(ksrc + i);
                float4 ct = {f2tf(t.x), f2tf(t.y), f2tf(t.z), f2tf(t.w)};
                *(float4*)&Ks[r * AP + d0 + i] = ct;
                float4 u = *(const float4*)(vsrc + i);
                float4 cu = {f2tf(u.x), f2tf(u.y), f2tf(u.z), f2tf(u.w)};
                *(float4*)&Vs[r * AP + d0 + i] = cu;
            }
        }
        __syncthreads();

        // S = Q K^T  (each warp: 16 rows x 32 cols)
        float sc[4][4];
#pragma unroll
        for (int nt = 0; nt < 4; nt++)
#pragma unroll
            for (int i = 0; i < 4; i++) sc[nt][i] = 0.f;

#pragma unroll
        for (int kk = 0; kk < 8; kk++) {
            uint32_t af[4], bf[4][2];
            const int kb = kk * 8;
            af[0] = __float_as_uint(Qs[(sm0 + g) * AP + kb + qq]);
            af[1] = __float_as_uint(Qs[(sm0 + g + 8) * AP + kb + qq]);
            af[2] = __float_as_uint(Qs[(sm0 + g) * AP + kb + qq + 4]);
            af[3] = __float_as_uint(Qs[(sm0 + g + 8) * AP + kb + qq + 4]);
#pragma unroll
            for (int nt = 0; nt < 4; nt++) {
                int n = sn0 + nt * 8 + g;
                bf[nt][0] = __float_as_uint(Ks[n * AP + kb + qq]);
                bf[nt][1] = __float_as_uint(Ks[n * AP + kb + qq + 4]);
            }
#pragma unroll
            for (int nt = 0; nt < 4; nt++)
                mma8(sc[nt], af, bf[nt]);
        }

        // Scale, causal mask, write S to smem
        const bool diag = (jt == qt);
#pragma unroll
        for (int nt = 0; nt < 4; nt++) {
            int r = sm0 + g;
            int c = sn0 + nt * 8 + 2 * qq;
            float v0 = sc[nt][0] * 0.125f, v1 = sc[nt][1] * 0.125f;
            float v2 = sc[nt][2] * 0.125f, v3 = sc[nt][3] * 0.125f;
            if (diag) {
                if (c     > r)     v0 = -1e30f;
                if (c + 1 > r)     v1 = -1e30f;
                if (c     > r + 8) v2 = -1e30f;
                if (c + 1 > r + 8) v3 = -1e30f;
            }
            *(float2*)&Ss[r * AP + c]       = make_float2(v0, v1);
            *(float2*)&Ss[(r + 8) * AP + c] = make_float2(v2, v3);
        }
        __syncthreads();

        // Online softmax: 4 threads per row (rows = tid>>2)
        {
            int row = tid >> 2;
            float* rp = Ss + row * AP + (tid & 3) * 16;
            float mold = m_s[row];
            float mm = mold;
#pragma unroll
            for (int i = 0; i < 16; i++) mm = fmaxf(mm, rp[i]);
            mm = fmaxf(mm, __shfl_xor_sync(0xffffffffu, mm, 1));
            mm = fmaxf(mm, __shfl_xor_sync(0xffffffffu, mm, 2));
            float sum = 0.f;
#pragma unroll
            for (int i = 0; i < 16; i++) {
                float pv = f2tf(__expf(rp[i] - mm));  // tf32-rounded prob
                rp[i] = pv;
                sum += pv;
            }
            sum += __shfl_xor_sync(0xffffffffu, sum, 1);
            sum += __shfl_xor_sync(0xffffffffu, sum, 2);
            if ((tid & 3) == 0) {
                float corr = __expf(mold - mm);
                l_s[row] = l_s[row] * corr + sum;
                m_s[row] = mm;
                c_s[row] = corr;
            }
        }
        __syncthreads();

        // Rescale accumulators, then O += P @ V
        {
            float c0f = c_s[sm0 + g];
            float c1f = c_s[sm0 + g + 8];
#pragma unroll
            for (int nt = 0; nt < 4; nt++) {
                oa[nt][0] *= c0f; oa[nt][1] *= c0f;
                oa[nt][2] *= c1f; oa[nt][3] *= c1f;
            }
        }

#pragma unroll
        for (int kk = 0; kk < 8; kk++) {
            uint32_t af[4], bf[4][2];
            const int kb = kk * 8;
            af[0] = __float_as_uint(Ss[(sm0 + g) * AP + kb + qq]);
            af[1] = __float_as_uint(Ss[(sm0 + g + 8) * AP + kb + qq]);
            af[2] = __float_as_uint(Ss[(sm0 + g) * AP + kb + qq + 4]);
            af[3] = __float_as_uint(Ss[(sm0 + g + 8) * AP + kb + qq + 4]);
#pragma unroll
            for (int nt = 0; nt < 4; nt++) {
                int n = sn0 + nt * 8 + g;
                bf[nt][0] = __float_as_uint(Vs[(kb + qq) * AP + n]);
                bf[nt][1] = __float_as_uint(Vs[(kb + qq + 4) * AP + n]);
            }
#pragma unroll
            for (int nt = 0; nt < 4; nt++)
                mma8(oa[nt], af, bf[nt]);
        }
    }

    // Finalize and store ctx in (B, L, H, D) layout
    {
        float il0 = 1.f / l_s[sm0 + g];
        float il1 = 1.f / l_s[sm0 + g + 8];
#pragma unroll
        for (int nt = 0; nt < 4; nt++) {
            int r = sm0 + g;
            int c = sn0 + nt * 8 + 2 * qq;
            size_t base0 = (((size_t)(b * CL + qt * 64 + r)) * CH + h) * CD + c;
            size_t base1 = (((size_t)(b * CL + qt * 64 + r + 8)) * CH + h) * CD + c;
            *(float2*)(ctx + base0) = make_float2(oa[nt][0] * il0, oa[nt][1] * il0);
            *(float2*)(ctx + base1) = make_float2(oa[nt][2] * il1, oa[nt][3] * il1);
        }
    }
}

// ---------------------------------------------------------------------------
// Launch
// ---------------------------------------------------------------------------
extern "C" void kernel_launch(void* const* d_in, const int* in_sizes, int n_in,
                              void* d_out, int out_size)
{
    const float* q_in = (const float*)d_in[0];
    const float* k_in = (const float*)d_in[1];
    const float* v_in = (const float*)d_in[2];
    // d_in[3] = attn_mask (causal tril, hardcoded)
    const float* Wq = (const float*)d_in[4];
    const float* Wk = (const float*)d_in[5];
    const float* Wv = (const float*)d_in[6];
    const float* Wo = (const float*)d_in[7];
    const float* bo = (const float*)d_in[8];
    float* out = (float*)d_out;

    float *pq, *pk, *pv, *pctx;
    cudaGetSymbolAddress((void**)&pq,   g_q);
    cudaGetSymbolAddress((void**)&pk,   g_k);
    cudaGetSymbolAddress((void**)&pv,   g_v);
    cudaGetSymbolAddress((void**)&pctx, g_ctx);

    cudaFuncSetAttribute(attn_kernel, cudaFuncAttributeMaxDynamicSharedMemorySize,
                         ATT_SMEM_BYTES);

    // Projections (tf32 tensor cores)
    dim3 gq(CE / 128, CM / 128);      // 16 x 32
    tgemm<false><<<gq, 256>>>(q_in, Wq, nullptr, pq, CM, CE, CE);
    dim3 gkv(KVE / 128, CM / 128);    // 4 x 32
    tgemm<false><<<gkv, 256>>>(k_in, Wk, nullptr, pk, CM, KVE, CE);
    tgemm<false><<<gkv, 256>>>(v_in, Wv, nullptr, pv, CM, KVE, CE);

    // RoPE on q and k
    {
        int npq = CB * CL * CH * (CD / 2);
        rope_kernel<<<(npq + 255) / 256, 256>>>(pq, CH, npq);
        int npk = CB * CL * CHKV * (CD / 2);
        rope_kernel<<<(npk + 255) / 256, 256>>>(pk, CHKV, npk);
    }

    // Attention (tf32 tensor cores)
    dim3 ga(CL / 64, CB * CH);        // 32 x 64
    attn_kernel<<<ga, 256, ATT_SMEM_BYTES>>>(pq, pk, pv, pctx);

    // Output projection + bias (tf32 tensor cores)
    tgemm<true><<<gq, 256>>>(pctx, Wo, bo, out, CM, CE, CE);
}

// round 4
// speedup vs baseline: 3.5614x; 1.7785x over previous
#include <cuda_runtime.h>
#include <cuda_fp16.h>
#include <math.h>
#include <stdint.h>

// Problem constants
#define CB   2
#define CL   2048
#define CE   2048
#define CH   32
#define CHKV 8
#define CD   64
#define CM   (CB*CL)
#define KVE  (CHKV*CD)

// Scratch (allocation-free rule: __device__ globals)
__device__ float g_q  [CB*CL*CE];
__device__ float g_k  [CB*CL*KVE];
__device__ float g_v  [CB*CL*KVE];
__device__ float g_ctx[CB*CL*CE];

// ---------------------------------------------------------------------------
// Helpers
// ---------------------------------------------------------------------------
__device__ __forceinline__ uint32_t s2u(const void* p) {
    return (uint32_t)__cvta_generic_to_shared(p);
}
__device__ __forceinline__ uint32_t packh2(float a, float b) {
    __half2 h = __floats2half2_rn(a, b);
    return *reinterpret_cast<uint32_t*>(&h);
}
__device__ __forceinline__ void ldsm_x4(uint32_t* r, uint32_t addr) {
    asm volatile("ldmatrix.sync.aligned.m8n8.x4.shared.b16 {%0,%1,%2,%3}, [%4];"
        : "=r"(r[0]), "=r"(r[1]), "=r"(r[2]), "=r"(r[3]) : "r"(addr));
}
__device__ __forceinline__ void ldsm_x2(uint32_t* r, uint32_t addr) {
    asm volatile("ldmatrix.sync.aligned.m8n8.x2.shared.b16 {%0,%1}, [%2];"
        : "=r"(r[0]), "=r"(r[1]) : "r"(addr));
}
__device__ __forceinline__ void ldsm_x2t(uint32_t* r, uint32_t addr) {
    asm volatile("ldmatrix.sync.aligned.m8n8.x2.trans.shared.b16 {%0,%1}, [%2];"
        : "=r"(r[0]), "=r"(r[1]) : "r"(addr));
}
__device__ __forceinline__ void mma16(float* c, const uint32_t* a, const uint32_t* b) {
    asm volatile(
        "mma.sync.aligned.m16n8k16.row.col.f32.f16.f16.f32 "
        "{%0,%1,%2,%3},{%4,%5,%6,%7},{%8,%9},{%0,%1,%2,%3};"
        : "+f"(c[0]), "+f"(c[1]), "+f"(c[2]), "+f"(c[3])
        : "r"(a[0]), "r"(a[1]), "r"(a[2]), "r"(a[3]), "r"(b[0]), "r"(b[1]));
}

// ---------------------------------------------------------------------------
// fp16 tensor-core GEMM: C[M,N] = A[M,K] @ W[K,N] (+bias), fp32 accumulate.
// BM=BN=128, BK=32, 256 threads (8 warps 2x4), register-staged double buffer.
// ---------------------------------------------------------------------------
#define ASTR 40    // halves per A smem row (32 + 8 pad)
#define BSTR 136   // halves per B smem row (128 + 8 pad)

template<bool BIAS>
__global__ __launch_bounds__(256)
void hgemm(const float* __restrict__ A, const float* __restrict__ W,
           const float* __restrict__ bias, float* __restrict__ C,
           int M, int N, int K)
{
    __shared__ __half As[128 * ASTR];   // [m][k]
    __shared__ __half Bs[32 * BSTR];    // [k][n]

    const int tid  = threadIdx.x;
    const int lane = tid & 31;
    const int warp = tid >> 5;
    const int g  = lane >> 2;
    const int qq = lane & 3;
    const int wm = (warp & 1) * 64;
    const int wn = (warp >> 1) * 32;
    const int row0 = blockIdx.y * 128;
    const int col0 = blockIdx.x * 128;

    const int ar = tid >> 1;            // A stage row 0..127
    const int ak = (tid & 1) * 16;      // A stage k offset
    const int bk = tid >> 3;            // B stage k row 0..31
    const int bn = (tid & 7) * 16;      // B stage n offset

    const float* Ap = A + (size_t)(row0 + ar) * K + ak;
    const float* Wp = W + (size_t)bk * N + col0 + bn;

    float areg[16], breg[16];
#pragma unroll
    for (int i = 0; i < 16; i += 4) {
        float4 t = *(const float4*)(Ap + i);
        areg[i] = t.x; areg[i+1] = t.y; areg[i+2] = t.z; areg[i+3] = t.w;
        float4 u = *(const float4*)(Wp + i);
        breg[i] = u.x; breg[i+1] = u.y; breg[i+2] = u.z; breg[i+3] = u.w;
    }
    Ap += 32;
    Wp += (size_t)32 * N;

    float acc[4][4][4];
#pragma unroll
    for (int mt = 0; mt < 4; mt++)
#pragma unroll
        for (int nt = 0; nt < 4; nt++)
#pragma unroll
            for (int i = 0; i < 4; i++) acc[mt][nt][i] = 0.f;

    const int ql = lane >> 3;
    const int lr = lane & 7;
    const uint32_t a_base = s2u(&As[(wm + (ql & 1) * 8 + lr) * ASTR + (ql >> 1) * 8]);
    const uint32_t b_base = s2u(&Bs[(lane & 15) * BSTR + wn]);

    const int nk = K >> 5;
    for (int it = 0; it < nk; it++) {
        // store staged regs to smem (fp16)
        {
            uint32_t p[8];
#pragma unroll
            for (int i = 0; i < 8; i++) p[i] = packh2(areg[2*i], areg[2*i+1]);
            *(uint4*)&As[ar * ASTR + ak]     = make_uint4(p[0], p[1], p[2], p[3]);
            *(uint4*)&As[ar * ASTR + ak + 8] = make_uint4(p[4], p[5], p[6], p[7]);
#pragma unroll
            for (int i = 0; i < 8; i++) p[i] = packh2(breg[2*i], breg[2*i+1]);
            *(uint4*)&Bs[bk * BSTR + bn]     = make_uint4(p[0], p[1], p[2], p[3]);
            *(uint4*)&Bs[bk * BSTR + bn + 8] = make_uint4(p[4], p[5], p[6], p[7]);
        }
        __syncthreads();

        if (it + 1 < nk) {
#pragma unroll
            for (int i = 0; i < 16; i += 4) {
                float4 t = *(const float4*)(Ap + i);
                areg[i] = t.x; areg[i+1] = t.y; areg[i+2] = t.z; areg[i+3] = t.w;
                float4 u = *(const float4*)(Wp + i);
                breg[i] = u.x; breg[i+1] = u.y; breg[i+2] = u.z; breg[i+3] = u.w;
            }
            Ap += 32;
            Wp += (size_t)32 * N;
        }

#pragma unroll
        for (int kc = 0; kc < 2; kc++) {
            uint32_t af[4][4], bf[4][2];
#pragma unroll
            for (int mt = 0; mt < 4; mt++)
                ldsm_x4(af[mt], a_base + (mt * 16 * ASTR + kc * 16) * 2);
#pragma unroll
            for (int nt = 0; nt < 4; nt++)
                ldsm_x2t(bf[nt], b_base + kc * 16 * BSTR * 2 + nt * 16);
#pragma unroll
            for (int mt = 0; mt < 4; mt++)
#pragma unroll
                for (int nt = 0; nt < 4; nt++)
                    mma16(acc[mt][nt], af[mt], bf[nt]);
        }
        __syncthreads();
    }

#pragma unroll
    for (int mt = 0; mt < 4; mt++) {
#pragma unroll
        for (int nt = 0; nt < 4; nt++) {
            int r = row0 + wm + mt * 16 + g;
            int c = col0 + wn + nt * 8 + 2 * qq;
            float2 v0 = {acc[mt][nt][0], acc[mt][nt][1]};
            float2 v1 = {acc[mt][nt][2], acc[mt][nt][3]};
            if (BIAS) {
                float b0 = bias[c], b1 = bias[c + 1];
                v0.x += b0; v0.y += b1;
                v1.x += b0; v1.y += b1;
            }
            *(float2*)(C + (size_t)r * N + c)       = v0;
            *(float2*)(C + (size_t)(r + 8) * N + c) = v1;
        }
    }
}

// ---------------------------------------------------------------------------
// RoPE in place. x layout (B, L, Hn, D), pairwise even/odd rotation.
// ---------------------------------------------------------------------------
__global__ void rope_kernel(float* __restrict__ x, int Hn, int npairs)
{
    int p = blockIdx.x * blockDim.x + threadIdx.x;
    if (p >= npairs) return;
    int d2   = p & 31;
    int rest = p >> 5;
    int l    = (rest / Hn) % CL;

    float inv = expf(-(float)(2 * d2) * (9.210340371976184f / 64.f));
    float fr  = (float)l * inv;
    float s, c;
    sincosf(fr, &s, &c);

    size_t base = (size_t)p * 2;
    float xe = x[base], xo = x[base + 1];
    x[base]     = xe * c - xo * s;
    x[base + 1] = xe * s + xo * c;
}

// ---------------------------------------------------------------------------
// Causal GQA flash attention, fp16 tensor cores, register-resident P and O.
// BQ=128 q-rows per block, BKV=64, D=64, 256 threads (8 warps x 16 rows).
// grid = (CL/128, B*H)
// ---------------------------------------------------------------------------
#define QSTR 72    // halves per smem row (64 + 8 pad)

__global__ __launch_bounds__(256)
void attn_kernel(const float* __restrict__ qg, const float* __restrict__ kg,
                 const float* __restrict__ vg, float* __restrict__ ctx)
{
    const int qt  = blockIdx.x;          // q tile (128 rows)
    const int bh  = blockIdx.y;
    const int b   = bh >> 5;
    const int h   = bh & 31;
    const int hkv = h >> 2;

    const int tid  = threadIdx.x;
    const int lane = tid & 31;
    const int warp = tid >> 5;
    const int g  = lane >> 2;
    const int qq = lane & 3;

    __shared__ __half sh[2 * 64 * QSTR];   // Ks | Vs  (also aliased for Q staging)
    __half* Ks = sh;              // [64][QSTR]  (kv row, d)
    __half* Vs = sh + 64 * QSTR;  // [64][QSTR]  (kv row, d)
    __half* Qs = sh;              // [128][QSTR] staging alias

    // ---- Stage Q (scaled by 1/8) to smem, coalesced ----
    {
        int r  = tid >> 1;
        int d0 = (tid & 1) * 32;
        const float* src = qg + (((size_t)(b * CL + qt * 128 + r)) * CH + h) * CD + d0;
#pragma unroll
        for (int j = 0; j < 4; j++) {
            float4 t0 = *(const float4*)(src + j * 8);
            float4 t1 = *(const float4*)(src + j * 8 + 4);
            uint4 pk;
            pk.x = packh2(t0.x * 0.125f, t0.y * 0.125f);
            pk.y = packh2(t0.z * 0.125f, t0.w * 0.125f);
            pk.z = packh2(t1.x * 0.125f, t1.y * 0.125f);
            pk.w = packh2(t1.z * 0.125f, t1.w * 0.125f);
            *(uint4*)&Qs[r * QSTR + d0 + j * 8] = pk;
        }
    }
    __syncthreads();

    // ---- Q fragments, register resident for whole kernel ----
    const int ql = lane >> 3;
    const int lr = lane & 7;
    uint32_t qf[4][4];
    {
        uint32_t qbase = s2u(&Qs[(warp * 16 + (ql & 1) * 8 + lr) * QSTR + (ql >> 1) * 8]);
#pragma unroll
        for (int kc = 0; kc < 4; kc++)
            ldsm_x4(qf[kc], qbase + kc * 32);
    }
    __syncthreads();   // Qs region free -> Ks/Vs

    float oa[8][4];
#pragma unroll
    for (int nt = 0; nt < 8; nt++)
#pragma unroll
        for (int i = 0; i < 4; i++) oa[nt][i] = 0.f;

    float m0 = -1e30f, m1 = -1e30f, l0 = 0.f, l1 = 0.f;
    const int row_g  = qt * 128 + warp * 16 + g;
    const int row_g8 = row_g + 8;
    const int wrow_max = qt * 128 + warp * 16 + 15;

    const uint32_t kbase = s2u(&Ks[(lane & 7) * QSTR + ((lane >> 3) & 1) * 8]);
    const uint32_t vbase = s2u(&Vs[(lane & 15) * QSTR]);

    const int jtmax = 2 * qt + 1;
    for (int jt = 0; jt <= jtmax; jt++) {
        __syncthreads();   // previous tile fully consumed

        // ---- Load K and V tiles (fp16, natural [kvrow][d]) ----
        {
            int r  = tid >> 2;
            int d0 = (tid & 3) * 16;
            size_t goff = (((size_t)(b * CL + jt * 64 + r)) * CHKV + hkv) * CD + d0;
            const float* ks = kg + goff;
            const float* vs = vg + goff;
            uint4 pk;
            float4 t0 = *(const float4*)(ks);
            float4 t1 = *(const float4*)(ks + 4);
            float4 t2 = *(const float4*)(ks + 8);
            float4 t3 = *(const float4*)(ks + 12);
            pk.x = packh2(t0.x, t0.y); pk.y = packh2(t0.z, t0.w);
            pk.z = packh2(t1.x, t1.y); pk.w = packh2(t1.z, t1.w);
            *(uint4*)&Ks[r * QSTR + d0] = pk;
            pk.x = packh2(t2.x, t2.y); pk.y = packh2(t2.z, t2.w);
            pk.z = packh2(t3.x, t3.y); pk.w = packh2(t3.z, t3.w);
            *(uint4*)&Ks[r * QSTR + d0 + 8] = pk;
            t0 = *(const float4*)(vs);
            t1 = *(const float4*)(vs + 4);
            t2 = *(const float4*)(vs + 8);
            t3 = *(const float4*)(vs + 12);
            pk.x = packh2(t0.x, t0.y); pk.y = packh2(t0.z, t0.w);
            pk.z = packh2(t1.x, t1.y); pk.w = packh2(t1.z, t1.w);
            *(uint4*)&Vs[r * QSTR + d0] = pk;
            pk.x = packh2(t2.x, t2.y); pk.y = packh2(t2.z, t2.w);
            pk.z = packh2(t3.x, t3.y); pk.w = packh2(t3.z, t3.w);
            *(uint4*)&Vs[r * QSTR + d0 + 8] = pk;
        }
        __syncthreads();

        // Fully-masked tile for this warp? skip compute (loads/syncs already done)
        if (jt * 64 > wrow_max) continue;

        // ---- S = Q K^T ----
        float sc[8][4];
#pragma unroll
        for (int nt = 0; nt < 8; nt++) {
            sc[nt][0] = 0.f; sc[nt][1] = 0.f; sc[nt][2] = 0.f; sc[nt][3] = 0.f;
#pragma unroll
            for (int kc = 0; kc < 4; kc++) {
                uint32_t bf[2];
                ldsm_x2(bf, kbase + nt * (8 * QSTR * 2) + kc * 32);
                mma16(sc[nt], qf[kc], bf);
            }
        }

        // ---- causal mask (only near diagonal) ----
        if (jt * 64 + 63 > row_g) {
#pragma unroll
            for (int nt = 0; nt < 8; nt++) {
                int c = jt * 64 + nt * 8 + 2 * qq;
                if (c     > row_g)  sc[nt][0] = -1e30f;
                if (c + 1 > row_g)  sc[nt][1] = -1e30f;
                if (c     > row_g8) sc[nt][2] = -1e30f;
                if (c + 1 > row_g8) sc[nt][3] = -1e30f;
            }
        }

        // ---- online softmax in registers (quad = same row) ----
        float mx0 = m0, mx1 = m1;
#pragma unroll
        for (int nt = 0; nt < 8; nt++) {
            mx0 = fmaxf(mx0, fmaxf(sc[nt][0], sc[nt][1]));
            mx1 = fmaxf(mx1, fmaxf(sc[nt][2], sc[nt][3]));
        }
        mx0 = fmaxf(mx0, __shfl_xor_sync(0xffffffffu, mx0, 1));
        mx0 = fmaxf(mx0, __shfl_xor_sync(0xffffffffu, mx0, 2));
        mx1 = fmaxf(mx1, __shfl_xor_sync(0xffffffffu, mx1, 1));
        mx1 = fmaxf(mx1, __shfl_xor_sync(0xffffffffu, mx1, 2));

        float s0 = 0.f, s1 = 0.f;
#pragma unroll
        for (int nt = 0; nt < 8; nt++) {
            sc[nt][0] = __expf(sc[nt][0] - mx0);
            sc[nt][1] = __expf(sc[nt][1] - mx0);
            sc[nt][2] = __expf(sc[nt][2] - mx1);
            sc[nt][3] = __expf(sc[nt][3] - mx1);
            s0 += sc[nt][0] + sc[nt][1];
            s1 += sc[nt][2] + sc[nt][3];
        }
        s0 += __shfl_xor_sync(0xffffffffu, s0, 1);
        s0 += __shfl_xor_sync(0xffffffffu, s0, 2);
        s1 += __shfl_xor_sync(0xffffffffu, s1, 1);
        s1 += __shfl_xor_sync(0xffffffffu, s1, 2);

        float corr0 = __expf(m0 - mx0);
        float corr1 = __expf(m1 - mx1);
        l0 = l0 * corr0 + s0;  m0 = mx0;
        l1 = l1 * corr1 + s1;  m1 = mx1;
#pragma unroll
        for (int nt = 0; nt < 8; nt++) {
            oa[nt][0] *= corr0; oa[nt][1] *= corr0;
            oa[nt][2] *= corr1; oa[nt][3] *= corr1;
        }

        // ---- P fragments (C layout == A layout identity) ----
        uint32_t pa[4][4];
#pragma unroll
        for (int kc = 0; kc < 4; kc++) {
            pa[kc][0] = packh2(sc[2*kc][0],   sc[2*kc][1]);
            pa[kc][1] = packh2(sc[2*kc][2],   sc[2*kc][3]);
            pa[kc][2] = packh2(sc[2*kc+1][0], sc[2*kc+1][1]);
            pa[kc][3] = packh2(sc[2*kc+1][2], sc[2*kc+1][3]);
        }

        // ---- O += P @ V ----
#pragma unroll
        for (int nt = 0; nt < 8; nt++) {
#pragma unroll
            for (int kc = 0; kc < 4; kc++) {
                uint32_t bf[2];
                ldsm_x2t(bf, vbase + kc * (16 * QSTR * 2) + nt * 16);
                mma16(oa[nt], pa[kc], bf);
            }
        }
    }

    // ---- finalize & store ctx (B, L, H, D) ----
    {
        float il0 = 1.f / l0;
        float il1 = 1.f / l1;
        size_t base0 = (((size_t)(b * CL + row_g))  * CH + h) * CD;
        size_t base1 = (((size_t)(b * CL + row_g8)) * CH + h) * CD;
#pragma unroll
        for (int nt = 0; nt < 8; nt++) {
            int c = nt * 8 + 2 * qq;
            *(float2*)(ctx + base0 + c) = make_float2(oa[nt][0] * il0, oa[nt][1] * il0);
            *(float2*)(ctx + base1 + c) = make_float2(oa[nt][2] * il1, oa[nt][3] * il1);
        }
    }
}

// ---------------------------------------------------------------------------
// Launch
// ---------------------------------------------------------------------------
extern "C" void kernel_launch(void* const* d_in, const int* in_sizes, int n_in,
                              void* d_out, int out_size)
{
    const float* q_in = (const float*)d_in[0];
    const float* k_in = (const float*)d_in[1];
    const float* v_in = (const float*)d_in[2];
    // d_in[3] = attn_mask (causal tril, hardcoded)
    const float* Wq = (const float*)d_in[4];
    const float* Wk = (const float*)d_in[5];
    const float* Wv = (const float*)d_in[6];
    const float* Wo = (const float*)d_in[7];
    const float* bo = (const float*)d_in[8];
    float* out = (float*)d_out;

    float *pq, *pk, *pv, *pctx;
    cudaGetSymbolAddress((void**)&pq,   g_q);
    cudaGetSymbolAddress((void**)&pk,   g_k);
    cudaGetSymbolAddress((void**)&pv,   g_v);
    cudaGetSymbolAddress((void**)&pctx, g_ctx);

    // Projections
    dim3 gq(CE / 128, CM / 128);      // 16 x 32
    hgemm<false><<<gq, 256>>>(q_in, Wq, nullptr, pq, CM, CE, CE);
    dim3 gkv(KVE / 128, CM / 128);    // 4 x 32
    hgemm<false><<<gkv, 256>>>(k_in, Wk, nullptr, pk, CM, KVE, CE);
    hgemm<false><<<gkv, 256>>>(v_in, Wv, nullptr, pv, CM, KVE, CE);

    // RoPE on q and k
    {
        int npq = CB * CL * CH * (CD / 2);
        rope_kernel<<<(npq + 255) / 256, 256>>>(pq, CH, npq);
        int npk = CB * CL * CHKV * (CD / 2);
        rope_kernel<<<(npk + 255) / 256, 256>>>(pk, CHKV, npk);
    }

    // Attention
    dim3 ga(CL / 128, CB * CH);       // 16 x 64
    attn_kernel<<<ga, 256>>>(pq, pk, pv, pctx);

    // Output projection + bias
    hgemm<true><<<gq, 256>>>(pctx, Wo, bo, out, CM, CE, CE);
}